// round 12
// baseline (speedup 1.0000x reference)
#include <cuda_runtime.h>
#include <cstdint>

// Problem shapes (fixed by the dataset)
#define ROWS      16384
#define PRED_COLS 100
#define TRUE_COLS 50
#define KK        50
#define TPB       256
#define WPB       (TPB / 32)        // 8 warps = 8 rows per block
#define NBLOCKS   (ROWS / WPB)      // 2048
#define FULL      0xFFFFFFFFu

// Scratch (allocation-free per harness rules)
__device__ float        g_partials[NBLOCKS];
__device__ unsigned int g_count = 0;   // reset by last block -> graph-replay-safe

__global__ __launch_bounds__(TPB) void mapk_warp_kernel(
    const int*   __restrict__ y_pred,
    const int*   __restrict__ y_true,
    const float* __restrict__ mult,
    float*       __restrict__ out)
{
    __shared__ unsigned int bmT[WPB][32];   // per-warp 1024-bit membership bitmap
    __shared__ float red[WPB];
    __shared__ unsigned int s_prev;

    const int tid  = threadIdx.x;
    const int w    = tid >> 5;
    const int lane = tid & 31;
    const bool act = (lane < 25);           // 25 lanes x 2 = 50 elements

    const int row = blockIdx.x * WPB + w;

    // ---- pair-per-lane vector loads: 3 wide LDGs (sentinel -1 -> bit 1023,
    //      which values <1000 never set) ----
    int2   P = make_int2(-1, -1);
    int2   T = make_int2(-1, -1);
    float2 M = make_float2(0.0f, 0.0f);
    if (act) {
        P = ((const int2*)(y_pred + (size_t)row * PRED_COLS))[lane];  // pos 2l, 2l+1
        T = ((const int2*)(y_true + (size_t)row * TRUE_COLS))[lane];
        M = ((const float2*)mult)[lane];                              // mult[2l], mult[2l+1]
    }

    // ---- build bitmap: zero own word, 2 spread-address atomicOr ----
    bmT[w][lane] = 0u;
    __syncwarp();
    if (act) {
        atomicOr(&bmT[w][((unsigned)T.x >> 5) & 31u], 1u << (T.x & 31));
        atomicOr(&bmT[w][((unsigned)T.y >> 5) & 31u], 1u << (T.y & 31));
    }
    __syncwarp();

    // ---- bitmap into registers: lane i owns word i (conflict-free LDS) ----
    const unsigned int myword = bmT[w][lane];

    // ---- membership via dynamic-source shfl -> (even, odd) match masks ----
    unsigned int wx = __shfl_sync(FULL, myword, ((unsigned)P.x >> 5));
    unsigned int wy = __shfl_sync(FULL, myword, ((unsigned)P.y >> 5));
    unsigned int mx = __ballot_sync(FULL, (wx >> (P.x & 31)) & 1u);   // even positions
    unsigned int my = __ballot_sync(FULL, (wy >> (P.y & 31)) & 1u);   // odd positions

    // ---- uniform scoring: globally-earliest remaining match each iter
    //      (ffs lane, even-before-odd); clearing all equal positions kills
    //      every future duplicate. All lanes compute identical score. ----
    float cnt = 0.0f, score = 0.0f;
    while (mx | my) {
        unsigned int c = mx | my;
        int  l0  = __ffs((int)c) - 1;
        bool evn = (mx >> l0) & 1u;                    // uniform
        int   v  = __shfl_sync(FULL, evn ? P.x : P.y, l0);
        float f  = __shfl_sync(FULL, evn ? M.x : M.y, l0);
        unsigned int ex = __ballot_sync(FULL, P.x == v);
        unsigned int ey = __ballot_sync(FULL, P.y == v);
        mx &= ~ex;                                     // clears scored bit + even dups
        my &= ~ey;                                     // clears odd dups
        cnt += 1.0f;
        score += cnt * f;
    }

    // ---- score is warp-uniform: lane 0 publishes; block reduce; finalize ----
    if (lane == 0) red[w] = score;
    __syncthreads();
    if (w == 0) {
        float v = (lane < WPB) ? red[lane] : 0.0f;
        #pragma unroll
        for (int off = WPB / 2; off > 0; off >>= 1)
            v += __shfl_down_sync(FULL, v, off);
        if (lane == 0) {
            g_partials[blockIdx.x] = v;
            __threadfence();
            s_prev = atomicAdd(&g_count, 1u);
        }
    }
    __syncthreads();

    if (s_prev == NBLOCKS - 1) {   // last block: deterministic final reduction
        __threadfence();
        float v = 0.0f;
        #pragma unroll
        for (int k = 0; k < NBLOCKS / TPB; ++k)   // 8 fixed-stride terms per thread
            v += g_partials[tid + k * TPB];
        #pragma unroll
        for (int off = 16; off > 0; off >>= 1)
            v += __shfl_down_sync(FULL, v, off);
        if (lane == 0) red[w] = v;
        __syncthreads();
        if (tid == 0) {
            float s = 0.0f;
            #pragma unroll
            for (int k = 0; k < WPB; ++k) s += red[k];
            out[0] = s * (1.0f / ((float)TRUE_COLS * (float)ROWS));
            g_count = 0;   // reset for next graph replay
        }
    }
}

extern "C" void kernel_launch(void* const* d_in, const int* in_sizes, int n_in,
                              void* d_out, int out_size)
{
    // Assign inputs by element count (robust to metadata ordering)
    const int*   y_pred = nullptr;
    const int*   y_true = nullptr;
    const float* mult   = nullptr;
    for (int i = 0; i < n_in; ++i) {
        if      (in_sizes[i] == ROWS * PRED_COLS) y_pred = (const int*)d_in[i];
        else if (in_sizes[i] == ROWS * TRUE_COLS) y_true = (const int*)d_in[i];
        else if (in_sizes[i] == KK)               mult   = (const float*)d_in[i];
    }
    float* out = (float*)d_out;

    mapk_warp_kernel<<<NBLOCKS, TPB>>>(y_pred, y_true, mult, out);
}